// round 5
// baseline (speedup 1.0000x reference)
#include <cuda_runtime.h>
#include <cstdint>

#define N_OBJ   8192
#define N_FLOOR 8192
#define STEPS   100

// Fixed constants matching the reference (all fp32)
#define DT_F        0.01f
#define TWO_R       0.002f
#define SLEEP_TH_F  0.098f        // DT * 9.8
#define EPS_F       1e-12f

// scratch: per-object min horizontal squared distance, stored as float bits
__device__ int g_min_bits[N_OBJ];

// ---------------------------------------------------------------------------
// Init: minxy2 = FLT_MAX
// ---------------------------------------------------------------------------
__global__ void init_min_kernel() {
    int i = blockIdx.x * blockDim.x + threadIdx.x;
    if (i < N_OBJ) g_min_bits[i] = 0x7F7FFFFF;   // FLT_MAX bits
}

// ---------------------------------------------------------------------------
// Kernel A: minxy2[i] = min_j ( (ox_i - fx_j)^2 + (oy_i - fy_j)^2 )
// grid = (N_OBJ/256, N_FLOOR/1024), block = 256 threads (1 obj each)
// ---------------------------------------------------------------------------
__global__ void __launch_bounds__(256) minxy_kernel(
    const float* __restrict__ obj, const float* __restrict__ flr)
{
    __shared__ float2 sf[1024];

    const int objIdx = blockIdx.x * 256 + threadIdx.x;
    const float ox = obj[objIdx * 3 + 0];
    const float oy = obj[objIdx * 3 + 1];

    const int fbase = blockIdx.y * 1024;
    for (int j = threadIdx.x; j < 1024; j += 256) {
        sf[j] = make_float2(flr[(fbase + j) * 3 + 0], flr[(fbase + j) * 3 + 1]);
    }
    __syncthreads();

    float m = __int_as_float(0x7F7FFFFF);
    #pragma unroll 8
    for (int j = 0; j < 1024; j++) {
        float dx = ox - sf[j].x;
        float dy = oy - sf[j].y;
        float d2 = fmaf(dy, dy, dx * dx);
        m = fminf(m, d2);
    }
    // d2 >= 0 so float ordering == int-bits ordering
    atomicMin(&g_min_bits[objIdx], __float_as_int(m));
}

// ---------------------------------------------------------------------------
// Kernel B: the 100-step rigid drop, single block of 1024 threads,
// 8 particles per thread held in registers.
// ---------------------------------------------------------------------------
__global__ void __launch_bounds__(1024) sim_kernel(
    const float* __restrict__ obj, float* __restrict__ out, int out_size)
{
    __shared__ float s_warpmin[32];
    __shared__ float s_mind2;

    const int tid = threadIdx.x;

    float z[8], mxy[8], tzf[8];
    bool  col[8];
    #pragma unroll
    for (int k = 0; k < 8; k++) {
        const int i = tid * 8 + k;
        z[k]   = obj[i * 3 + 2];
        mxy[k] = __int_as_float(g_min_bits[i]);
        col[k] = false;
        tzf[k] = 0.0f;
    }

    float tz = 0.0f, vz = 0.0f;
    bool asleep = false;

    const float GDT = -9.8f * DT_F;

    for (int s = 0; s < STEPS && !asleep; s++) {
        // semi-implicit Euler (vertical only; xy stay exactly 0)
        const float vzn = vz + GDT;
        const float tzn = tz + vzn * DT_F;

        // per-particle d2min = minxy2 + dz^2 ; block min
        float d2[8];
        float lmin = __int_as_float(0x7F7FFFFF);
        #pragma unroll
        for (int k = 0; k < 8; k++) {
            const float dz = z[k] + tzn;
            d2[k] = fmaf(dz, dz, mxy[k]);
            lmin = fminf(lmin, d2[k]);
        }
        #pragma unroll
        for (int o = 16; o > 0; o >>= 1)
            lmin = fminf(lmin, __shfl_xor_sync(0xFFFFFFFFu, lmin, o));
        if ((tid & 31) == 0) s_warpmin[tid >> 5] = lmin;
        __syncthreads();
        if (tid < 32) {
            float v = s_warpmin[tid];
            #pragma unroll
            for (int o = 16; o > 0; o >>= 1)
                v = fminf(v, __shfl_xor_sync(0xFFFFFFFFu, v, o));
            if (tid == 0) s_mind2 = v;
        }
        __syncthreads();
        const float mind2 = s_mind2;

        // max_pen = 2R - min_i dmin_i  (min commutes through monotone sqrt)
        const float dmin   = sqrtf(mind2 + EPS_F);
        const float maxpen = TWO_R - dmin;
        const bool  any_c  = maxpen > 0.0f;

        const float tzc = any_c ? (tzn + maxpen) : tzn;
        const float vzc = any_c ? 0.0f : vzn;

        if (any_c) {
            // record first-contact positions (rare path: happens ~once)
            #pragma unroll
            for (int k = 0; k < 8; k++) {
                const float pk = TWO_R - sqrtf(d2[k] + EPS_F);
                if (pk > 0.0f && !col[k]) {
                    col[k] = true;
                    tzf[k] = tzc;
                }
            }
        }

        asleep = any_c && (fabsf(vzc) < SLEEP_TH_F);   // uniform across block
        tz = tzc;
        vz = vzc;
    }

    // outputs: p_first [N,3] (float32), then collision mask as 0/1 floats
    const int mask_off = out_size - N_OBJ;
    #pragma unroll
    for (int k = 0; k < 8; k++) {
        const int i = tid * 8 + k;
        const float px = obj[i * 3 + 0];
        const float py = obj[i * 3 + 1];
        float pz = z[k];
        if (col[k]) pz = z[k] + tzf[k];
        out[i * 3 + 0] = px;
        out[i * 3 + 1] = py;
        out[i * 3 + 2] = pz;
        if (out_size >= N_OBJ * 4)
            out[mask_off + i] = col[k] ? 1.0f : 0.0f;
    }
}

// ---------------------------------------------------------------------------
extern "C" void kernel_launch(void* const* d_in, const int* in_sizes, int n_in,
                              void* d_out, int out_size)
{
    const float* obj = (const float*)d_in[0];   // [8192,3]
    const float* flr = (const float*)d_in[1];   // [8192,3]
    float* out = (float*)d_out;

    init_min_kernel<<<N_OBJ / 256, 256>>>();
    dim3 grid(N_OBJ / 256, N_FLOOR / 1024);
    minxy_kernel<<<grid, 256>>>(obj, flr);
    sim_kernel<<<1, 1024>>>(obj, out, out_size);
}